// round 10
// baseline (speedup 1.0000x reference)
#include <cuda_runtime.h>

#define NN 100000
#define NF 512
#define NH 16
#define NC 40
#define NE 3200000
#define KCH 4            // split-K chunks
#define KC  (NF / KCH)   // 128 cols per chunk
#define SCB 1024         // scan block size
#define NSB ((NN + SCB - 1) / SCB)   // 98 scan blocks

// Scratch (no allocations allowed -> __device__ globals)
__device__ float g_dinv[NN];
__device__ float g_feat[NN * NH];       // layer-1 messages, later final agg2
__device__ float g_agg[NN * NH];        // layer-2 messages
__device__ float g_part[KCH][NN * NH];  // split-K partials (deterministic)
__device__ int   g_deg[NN];
__device__ int   g_scan[NN];            // block-local inclusive scan
__device__ int   g_rows[NN + 1];        // CSR row offsets
__device__ int   g_cursor[NN];          // fill cursors
__device__ int   g_csr[NE];             // CSR column (src) indices
__device__ int   g_bsum[NSB];
__device__ int   g_boff[NSB];

// ---------------------------------------------------------------- degree
__global__ void k_zero() {
    int i = blockIdx.x * blockDim.x + threadIdx.x;
    if (i < NN) g_deg[i] = 0;
}

// 4 edges per thread via int4 (NE % 4 == 0)
__global__ void k_deg(const int* __restrict__ dst) {
    int e4 = blockIdx.x * blockDim.x + threadIdx.x;
    if (e4 >= NE / 4) return;
    int4 d = reinterpret_cast<const int4*>(dst)[e4];
    atomicAdd(&g_deg[d.x], 1);
    atomicAdd(&g_deg[d.y], 1);
    atomicAdd(&g_deg[d.z], 1);
    atomicAdd(&g_deg[d.w], 1);
}

// ---------------------------------------------------------------- prefix scan (3 stages)
__global__ __launch_bounds__(SCB) void k_scan1() {
    __shared__ int s[SCB];
    int t = threadIdx.x;
    int i = blockIdx.x * SCB + t;
    int v = (i < NN) ? g_deg[i] : 0;
    s[t] = v;
    __syncthreads();
#pragma unroll
    for (int off = 1; off < SCB; off <<= 1) {
        int u = (t >= off) ? s[t - off] : 0;
        __syncthreads();
        s[t] += u;
        __syncthreads();
    }
    if (i < NN) g_scan[i] = s[t];
    if (t == SCB - 1) g_bsum[blockIdx.x] = s[t];
}

__global__ __launch_bounds__(128) void k_scan2() {
    __shared__ int s[128];
    int t = threadIdx.x;
    int v = (t < NSB) ? g_bsum[t] : 0;
    s[t] = v;
    __syncthreads();
#pragma unroll
    for (int off = 1; off < 128; off <<= 1) {
        int u = (t >= off) ? s[t - off] : 0;
        __syncthreads();
        s[t] += u;
        __syncthreads();
    }
    if (t < NSB) g_boff[t] = s[t] - v;   // exclusive block offsets
}

__global__ void k_scan3() {
    int i = blockIdx.x * blockDim.x + threadIdx.x;
    if (i >= NN) return;
    int d = g_deg[i];
    int excl = g_scan[i] - d + g_boff[i >> 10];
    g_rows[i] = excl;
    g_cursor[i] = excl;
    g_dinv[i] = rsqrtf((float)(d + 1));   // +1 self-loop
    if (i == 0) g_rows[NN] = NE;
}

// ---------------------------------------------------------------- CSR fill (4 edges/thread)
__global__ void k_fill(const int* __restrict__ src, const int* __restrict__ dst) {
    int e4 = blockIdx.x * blockDim.x + threadIdx.x;
    if (e4 >= NE / 4) return;
    int4 s = reinterpret_cast<const int4*>(src)[e4];
    int4 d = reinterpret_cast<const int4*>(dst)[e4];
    g_csr[atomicAdd(&g_cursor[d.x], 1)] = s.x;
    g_csr[atomicAdd(&g_cursor[d.y], 1)] = s.y;
    g_csr[atomicAdd(&g_cursor[d.z], 1)] = s.z;
    g_csr[atomicAdd(&g_cursor[d.w], 1)] = s.w;
}

// ---------------------------------------------------------------- GEMM1 (split-K, 4 nodes/thread):
// grid (98, 4), 256 threads, 2 CTAs/SM. CTA (b,c): nodes [b*1024, +1024),
// k-cols [c*128, +128). One broadcast LDS.64 of W feeds 4 FMA2s -> smem pipe
// time ~23us, below the ~38us DRAM floor for streaming x.
__global__ __launch_bounds__(256, 2) void k_gemm1(const float* __restrict__ x,
                                                  const float* __restrict__ W1) {
    __shared__ float Ws[KC * NH];    // 8 KB
    const int tid   = threadIdx.x;
    const int chunk = blockIdx.y;
    const int base  = blockIdx.x * 1024;

    for (int i = tid; i < KC * NH; i += 256) Ws[i] = W1[chunk * KC * NH + i];
    __syncthreads();
    const unsigned long long* Ws2 = reinterpret_cast<const unsigned long long*>(Ws);

    int n[4];
    const float4* xp[4];
#pragma unroll
    for (int i = 0; i < 4; i++) {
        n[i] = base + tid + i * 256;
        int m = n[i] < NN ? n[i] : 0;
        xp[i] = reinterpret_cast<const float4*>(x + (size_t)m * NF + chunk * KC);
    }

    unsigned long long acc[4][8];
#pragma unroll
    for (int i = 0; i < 4; i++)
#pragma unroll
        for (int j = 0; j < 8; j++) acc[i][j] = 0ull;

#pragma unroll 2
    for (int it = 0; it < KC / 4; it++) {     // 32 iters, 4 k-cols each
        float4 v[4];
#pragma unroll
        for (int i = 0; i < 4; i++) v[i] = xp[i][it];   // 4 batched LDG.128
#pragma unroll
        for (int c = 0; c < 4; c++) {
            const int k = it * 4 + c;
            unsigned long long xx[4];
            {
                float f0 = c == 0 ? v[0].x : c == 1 ? v[0].y : c == 2 ? v[0].z : v[0].w;
                float f1 = c == 0 ? v[1].x : c == 1 ? v[1].y : c == 2 ? v[1].z : v[1].w;
                float f2 = c == 0 ? v[2].x : c == 1 ? v[2].y : c == 2 ? v[2].z : v[2].w;
                float f3 = c == 0 ? v[3].x : c == 1 ? v[3].y : c == 2 ? v[3].z : v[3].w;
                asm("mov.b64 %0, {%1, %1};" : "=l"(xx[0]) : "r"(__float_as_uint(f0)));
                asm("mov.b64 %0, {%1, %1};" : "=l"(xx[1]) : "r"(__float_as_uint(f1)));
                asm("mov.b64 %0, {%1, %1};" : "=l"(xx[2]) : "r"(__float_as_uint(f2)));
                asm("mov.b64 %0, {%1, %1};" : "=l"(xx[3]) : "r"(__float_as_uint(f3)));
            }
#pragma unroll
            for (int j = 0; j < 8; j++) {
                unsigned long long w2 = Ws2[k * 8 + j];   // broadcast LDS.64
                asm("fma.rn.f32x2 %0, %1, %2, %0;" : "+l"(acc[0][j]) : "l"(xx[0]), "l"(w2));
                asm("fma.rn.f32x2 %0, %1, %2, %0;" : "+l"(acc[1][j]) : "l"(xx[1]), "l"(w2));
                asm("fma.rn.f32x2 %0, %1, %2, %0;" : "+l"(acc[2][j]) : "l"(xx[2]), "l"(w2));
                asm("fma.rn.f32x2 %0, %1, %2, %0;" : "+l"(acc[3][j]) : "l"(xx[3]), "l"(w2));
            }
        }
    }

#pragma unroll
    for (int i = 0; i < 4; i++) {
        if (n[i] >= NN) continue;
        float4* p = (float4*)(&g_part[chunk][(size_t)n[i] * NH]);
#pragma unroll
        for (int q = 0; q < 4; q++) {
            unsigned lo0, hi0, lo1, hi1;
            asm("mov.b64 {%0, %1}, %2;" : "=r"(lo0), "=r"(hi0) : "l"(acc[i][2*q]));
            asm("mov.b64 {%0, %1}, %2;" : "=r"(lo1), "=r"(hi1) : "l"(acc[i][2*q+1]));
            p[q] = make_float4(__uint_as_float(lo0), __uint_as_float(hi0),
                               __uint_as_float(lo1), __uint_as_float(hi1));
        }
    }
}

// ---------------------------------------------------------------- combine: feat = (sum parts) * dinv
__global__ void k_combine() {
    int i = blockIdx.x * blockDim.x + threadIdx.x;
    if (i >= NN) return;
    float dv = g_dinv[i];
    const float4* p0 = (const float4*)(&g_part[0][(size_t)i * NH]);
    const float4* p1 = (const float4*)(&g_part[1][(size_t)i * NH]);
    const float4* p2 = (const float4*)(&g_part[2][(size_t)i * NH]);
    const float4* p3 = (const float4*)(&g_part[3][(size_t)i * NH]);
    float4* f = (float4*)(g_feat + (size_t)i * NH);
#pragma unroll
    for (int q = 0; q < 4; q++) {
        float4 s0 = p0[q], s1 = p1[q], s2 = p2[q], s3 = p3[q];
        float4 v;
        v.x = ((s0.x + s1.x) + (s2.x + s3.x)) * dv;
        v.y = ((s0.y + s1.y) + (s2.y + s3.y)) * dv;
        v.z = ((s0.z + s1.z) + (s2.z + s3.z)) * dv;
        v.w = ((s0.w + s1.w) + (s2.w + s3.w)) * dv;
        f[q] = v;
    }
}

// ---------------------------------------------------------------- CSR gather (warp per node)
// 16 lanes per neighbor: lane (half, f) reads in[nb*16+f] (64B coalesced per
// half-warp). acc register chain, shfl-reduce across halves.
// mode 0 (layer 1): out = relu(dinv*acc + b1) * dinv  -> g_agg (layer-2 msgs)
// mode 1 (layer 2): out = dinv*acc                    -> g_feat (final agg2)
__global__ __launch_bounds__(256) void k_gather(const float* __restrict__ b1, int mode) {
    int w = (blockIdx.x * 256 + threadIdx.x) >> 5;
    if (w >= NN) return;
    const int lane = threadIdx.x & 31;
    const int half = lane >> 4;
    const int f    = lane & 15;

    const float* __restrict__ in = mode ? g_agg : g_feat;
    int rs = g_rows[w], re = g_rows[w + 1];

    // self term counted once (half 0 only)
    float acc0 = half ? 0.0f : in[(size_t)w * NH + f];
    float acc1 = 0.0f;

    int c = rs;
    // 4 neighbors per iteration (2 per half), 2 independent accumulator chains
    for (; c + 4 <= re; c += 4) {
        int nb0 = __ldg(&g_csr[c + half]);
        int nb1 = __ldg(&g_csr[c + 2 + half]);
        float v0 = in[(size_t)nb0 * NH + f];
        float v1 = in[(size_t)nb1 * NH + f];
        acc0 += v0;
        acc1 += v1;
    }
    for (; c + half < re; c += 2) {
        int nb = __ldg(&g_csr[c + half]);
        acc0 += in[(size_t)nb * NH + f];
    }
    float acc = acc0 + acc1;
    acc += __shfl_down_sync(0xffffffffu, acc, 16);

    if (lane < 16) {
        float dv = g_dinv[w];
        float v = acc * dv;
        if (mode == 0) {
            v = fmaxf(v + __ldg(&b1[f]), 0.0f) * dv;
            g_agg[(size_t)w * NH + f] = v;
        } else {
            g_feat[(size_t)w * NH + f] = v;
        }
    }
}

// ---------------------------------------------------------------- out: log_softmax(agg2 @ W2 + b2)
__global__ __launch_bounds__(256) void k_out(const float* __restrict__ W2,
                                             const float* __restrict__ b2,
                                             float* __restrict__ out) {
    __shared__ float Ws[NH * NC];   // 2.5 KB
    __shared__ float bs[NC];
    int tid = threadIdx.x;
    for (int i = tid; i < NH * NC; i += 256) Ws[i] = W2[i];
    if (tid < NC) bs[tid] = b2[tid];
    __syncthreads();

    int i = blockIdx.x * 256 + tid;
    if (i >= NN) return;

    float v[NH];
    const float4* a = (const float4*)(g_feat + (size_t)i * NH);
#pragma unroll
    for (int q = 0; q < 4; q++) {
        float4 t = a[q];
        v[4*q+0] = t.x; v[4*q+1] = t.y; v[4*q+2] = t.z; v[4*q+3] = t.w;
    }

    float o[NC];
    float m = -1e30f;
#pragma unroll
    for (int k = 0; k < NC; k++) {
        float s = bs[k];
#pragma unroll
        for (int j = 0; j < NH; j++) s = fmaf(v[j], Ws[j * NC + k], s);
        o[k] = s;
        m = fmaxf(m, s);
    }
    float sum = 0.f;
#pragma unroll
    for (int k = 0; k < NC; k++) sum += __expf(o[k] - m);
    float l = m + logf(sum);

    float4* op = (float4*)(out + (size_t)i * NC);
#pragma unroll
    for (int q = 0; q < 10; q++) {
        op[q] = make_float4(o[4*q] - l, o[4*q+1] - l, o[4*q+2] - l, o[4*q+3] - l);
    }
}

// ----------------------------------------------------------------
extern "C" void kernel_launch(void* const* d_in, const int* in_sizes, int n_in,
                              void* d_out, int out_size) {
    const float* x  = (const float*)d_in[0];
    const int*   ei = (const int*)d_in[1];
    const float* W1 = (const float*)d_in[2];
    const float* b1 = (const float*)d_in[3];
    const float* W2 = (const float*)d_in[4];
    const float* b2 = (const float*)d_in[5];
    float* out = (float*)d_out;

    const int* src = ei;        // edge_index[0]
    const int* dst = ei + NE;   // edge_index[1]

    const int NB_N  = (NN + 255) / 256;        // 391
    const int NB_E4 = (NE / 4 + 255) / 256;    // 3125
    const int NB_W  = (NN * 32 + 255) / 256;   // 12500 (warp per node)

    k_zero<<<NB_N, 256>>>();
    k_deg<<<NB_E4, 256>>>(dst);
    k_scan1<<<NSB, SCB>>>();
    k_scan2<<<1, 128>>>();
    k_scan3<<<NB_N, 256>>>();
    k_fill<<<NB_E4, 256>>>(src, dst);
    k_gemm1<<<dim3((NN + 1023) / 1024, KCH), 256>>>(x, W1);
    k_combine<<<NB_N, 256>>>();
    k_gather<<<NB_W, 256>>>(b1, 0);   // layer 1 aggregate + relu + rescale
    k_gather<<<NB_W, 256>>>(b1, 1);   // layer 2 aggregate
    k_out<<<NB_N, 256>>>(W2, b2, out);
}

// round 12
// speedup vs baseline: 1.0781x; 1.0781x over previous
#include <cuda_runtime.h>

#define NN 100000
#define NF 512
#define NH 16
#define NC 40
#define NE 3200000
#define KCH 4            // split-K chunks
#define KC  (NF / KCH)   // 128 cols per chunk
#define SCB 1024         // scan block size
#define NSB ((NN + SCB - 1) / SCB)   // 98 scan blocks

// Scratch (no allocations allowed -> __device__ globals)
__device__ float g_dinv[NN];
__device__ float g_feat[NN * NH];       // layer-1 messages, later final agg2
__device__ float g_agg[NN * NH];        // layer-2 messages
__device__ float g_part[KCH][NN * NH];  // split-K partials (deterministic)
__device__ int   g_deg[NN];
__device__ int   g_scan[NN];            // block-local inclusive scan
__device__ int   g_rows[NN + 1];        // CSR row offsets
__device__ int   g_cursor[NN];          // fill cursors
__device__ int   g_csr[NE];             // CSR column (src) indices
__device__ int   g_bsum[NSB];
__device__ int   g_boff[NSB];

// ---------------------------------------------------------------- degree
__global__ void k_zero() {
    int i = blockIdx.x * blockDim.x + threadIdx.x;
    if (i < NN) g_deg[i] = 0;
}

// 4 edges per thread via int4 (NE % 4 == 0)
__global__ void k_deg(const int* __restrict__ dst) {
    int e4 = blockIdx.x * blockDim.x + threadIdx.x;
    if (e4 >= NE / 4) return;
    int4 d = reinterpret_cast<const int4*>(dst)[e4];
    atomicAdd(&g_deg[d.x], 1);
    atomicAdd(&g_deg[d.y], 1);
    atomicAdd(&g_deg[d.z], 1);
    atomicAdd(&g_deg[d.w], 1);
}

// ---------------------------------------------------------------- prefix scan (3 stages)
__global__ __launch_bounds__(SCB) void k_scan1() {
    __shared__ int s[SCB];
    int t = threadIdx.x;
    int i = blockIdx.x * SCB + t;
    int v = (i < NN) ? g_deg[i] : 0;
    s[t] = v;
    __syncthreads();
#pragma unroll
    for (int off = 1; off < SCB; off <<= 1) {
        int u = (t >= off) ? s[t - off] : 0;
        __syncthreads();
        s[t] += u;
        __syncthreads();
    }
    if (i < NN) g_scan[i] = s[t];
    if (t == SCB - 1) g_bsum[blockIdx.x] = s[t];
}

__global__ __launch_bounds__(128) void k_scan2() {
    __shared__ int s[128];
    int t = threadIdx.x;
    int v = (t < NSB) ? g_bsum[t] : 0;
    s[t] = v;
    __syncthreads();
#pragma unroll
    for (int off = 1; off < 128; off <<= 1) {
        int u = (t >= off) ? s[t - off] : 0;
        __syncthreads();
        s[t] += u;
        __syncthreads();
    }
    if (t < NSB) g_boff[t] = s[t] - v;   // exclusive block offsets
}

__global__ void k_scan3() {
    int i = blockIdx.x * blockDim.x + threadIdx.x;
    if (i >= NN) return;
    int d = g_deg[i];
    int excl = g_scan[i] - d + g_boff[i >> 10];
    g_rows[i] = excl;
    g_cursor[i] = excl;
    g_dinv[i] = rsqrtf((float)(d + 1));   // +1 self-loop
    if (i == 0) g_rows[NN] = NE;
}

// ---------------------------------------------------------------- CSR fill (4 edges/thread)
__global__ void k_fill(const int* __restrict__ src, const int* __restrict__ dst) {
    int e4 = blockIdx.x * blockDim.x + threadIdx.x;
    if (e4 >= NE / 4) return;
    int4 s = reinterpret_cast<const int4*>(src)[e4];
    int4 d = reinterpret_cast<const int4*>(dst)[e4];
    g_csr[atomicAdd(&g_cursor[d.x], 1)] = s.x;
    g_csr[atomicAdd(&g_cursor[d.y], 1)] = s.y;
    g_csr[atomicAdd(&g_cursor[d.z], 1)] = s.z;
    g_csr[atomicAdd(&g_cursor[d.w], 1)] = s.w;
}

// ---------------------------------------------------------------- GEMM1 (split-K, 2 nodes/thread):
// grid (196, 4), 256 threads. CTA (b,c): nodes [b*512, +512), k-cols [c*128, +128).
// W row loaded as 4x LDS.128 broadcast (halves shared-pipe wavefronts vs LDS.64);
// each W value feeds 2 FMA2s (2 nodes). FMA floor 23us, DRAM floor ~38us.
__global__ __launch_bounds__(256) void k_gemm1(const float* __restrict__ x,
                                               const float* __restrict__ W1) {
    __shared__ __align__(16) float Ws[KC * NH];    // 8 KB
    const int tid   = threadIdx.x;
    const int chunk = blockIdx.y;
    const int n0 = blockIdx.x * 512 + tid;
    const int n1 = n0 + 256;

    for (int i = tid; i < KC * NH; i += 256) Ws[i] = W1[chunk * KC * NH + i];
    __syncthreads();
    const ulonglong2* Ws4 = reinterpret_cast<const ulonglong2*>(Ws);  // 16B granules

    const int m0 = n0 < NN ? n0 : 0;
    const int m1 = n1 < NN ? n1 : 0;
    const float4* xa = reinterpret_cast<const float4*>(x + (size_t)m0 * NF + chunk * KC);
    const float4* xb = reinterpret_cast<const float4*>(x + (size_t)m1 * NF + chunk * KC);

    unsigned long long accA[8], accB[8];
#pragma unroll
    for (int j = 0; j < 8; j++) { accA[j] = 0ull; accB[j] = 0ull; }

#pragma unroll 2
    for (int it = 0; it < KC / 8; it++) {       // 16 iters, 8 k-cols each
        float4 a0 = xa[it * 2], a1 = xa[it * 2 + 1];    // 4 batched LDG.128
        float4 b0 = xb[it * 2], b1 = xb[it * 2 + 1];
        float av[8] = {a0.x, a0.y, a0.z, a0.w, a1.x, a1.y, a1.z, a1.w};
        float bv[8] = {b0.x, b0.y, b0.z, b0.w, b1.x, b1.y, b1.z, b1.w};
#pragma unroll
        for (int c = 0; c < 8; c++) {
            const int k = it * 8 + c;
            unsigned long long a2, b2;
            asm("mov.b64 %0, {%1, %1};" : "=l"(a2) : "r"(__float_as_uint(av[c])));
            asm("mov.b64 %0, {%1, %1};" : "=l"(b2) : "r"(__float_as_uint(bv[c])));
            // W row k: 64B as 4x LDS.128 broadcast
            ulonglong2 w01 = Ws4[k * 4 + 0];
            ulonglong2 w23 = Ws4[k * 4 + 1];
            ulonglong2 w45 = Ws4[k * 4 + 2];
            ulonglong2 w67 = Ws4[k * 4 + 3];
            asm("fma.rn.f32x2 %0, %1, %2, %0;" : "+l"(accA[0]) : "l"(a2), "l"(w01.x));
            asm("fma.rn.f32x2 %0, %1, %2, %0;" : "+l"(accB[0]) : "l"(b2), "l"(w01.x));
            asm("fma.rn.f32x2 %0, %1, %2, %0;" : "+l"(accA[1]) : "l"(a2), "l"(w01.y));
            asm("fma.rn.f32x2 %0, %1, %2, %0;" : "+l"(accB[1]) : "l"(b2), "l"(w01.y));
            asm("fma.rn.f32x2 %0, %1, %2, %0;" : "+l"(accA[2]) : "l"(a2), "l"(w23.x));
            asm("fma.rn.f32x2 %0, %1, %2, %0;" : "+l"(accB[2]) : "l"(b2), "l"(w23.x));
            asm("fma.rn.f32x2 %0, %1, %2, %0;" : "+l"(accA[3]) : "l"(a2), "l"(w23.y));
            asm("fma.rn.f32x2 %0, %1, %2, %0;" : "+l"(accB[3]) : "l"(b2), "l"(w23.y));
            asm("fma.rn.f32x2 %0, %1, %2, %0;" : "+l"(accA[4]) : "l"(a2), "l"(w45.x));
            asm("fma.rn.f32x2 %0, %1, %2, %0;" : "+l"(accB[4]) : "l"(b2), "l"(w45.x));
            asm("fma.rn.f32x2 %0, %1, %2, %0;" : "+l"(accA[5]) : "l"(a2), "l"(w45.y));
            asm("fma.rn.f32x2 %0, %1, %2, %0;" : "+l"(accB[5]) : "l"(b2), "l"(w45.y));
            asm("fma.rn.f32x2 %0, %1, %2, %0;" : "+l"(accA[6]) : "l"(a2), "l"(w67.x));
            asm("fma.rn.f32x2 %0, %1, %2, %0;" : "+l"(accB[6]) : "l"(b2), "l"(w67.x));
            asm("fma.rn.f32x2 %0, %1, %2, %0;" : "+l"(accA[7]) : "l"(a2), "l"(w67.y));
            asm("fma.rn.f32x2 %0, %1, %2, %0;" : "+l"(accB[7]) : "l"(b2), "l"(w67.y));
        }
    }

#pragma unroll
    for (int half = 0; half < 2; half++) {
        int node = half ? n1 : n0;
        if (node >= NN) continue;
        unsigned long long* acc = half ? accB : accA;
        float4* p = (float4*)(&g_part[chunk][(size_t)node * NH]);
#pragma unroll
        for (int q = 0; q < 4; q++) {
            unsigned lo0, hi0, lo1, hi1;
            asm("mov.b64 {%0, %1}, %2;" : "=r"(lo0), "=r"(hi0) : "l"(acc[2*q]));
            asm("mov.b64 {%0, %1}, %2;" : "=r"(lo1), "=r"(hi1) : "l"(acc[2*q+1]));
            p[q] = make_float4(__uint_as_float(lo0), __uint_as_float(hi0),
                               __uint_as_float(lo1), __uint_as_float(hi1));
        }
    }
}

// ---------------------------------------------------------------- combine: feat = (sum parts) * dinv
__global__ void k_combine() {
    int i = blockIdx.x * blockDim.x + threadIdx.x;
    if (i >= NN) return;
    float dv = g_dinv[i];
    const float4* p0 = (const float4*)(&g_part[0][(size_t)i * NH]);
    const float4* p1 = (const float4*)(&g_part[1][(size_t)i * NH]);
    const float4* p2 = (const float4*)(&g_part[2][(size_t)i * NH]);
    const float4* p3 = (const float4*)(&g_part[3][(size_t)i * NH]);
    float4* f = (float4*)(g_feat + (size_t)i * NH);
#pragma unroll
    for (int q = 0; q < 4; q++) {
        float4 s0 = p0[q], s1 = p1[q], s2 = p2[q], s3 = p3[q];
        float4 v;
        v.x = ((s0.x + s1.x) + (s2.x + s3.x)) * dv;
        v.y = ((s0.y + s1.y) + (s2.y + s3.y)) * dv;
        v.z = ((s0.z + s1.z) + (s2.z + s3.z)) * dv;
        v.w = ((s0.w + s1.w) + (s2.w + s3.w)) * dv;
        f[q] = v;
    }
}

// ---------------------------------------------------------------- CSR gather (warp per node)
// 16 lanes per neighbor: lane (half, f) reads in[nb*16+f] (64B coalesced per
// half-warp). 4 independent accumulator chains (8 neighbors in flight/warp).
// mode 0 (layer 1): out = relu(dinv*acc + b1) * dinv  -> g_agg (layer-2 msgs)
// mode 1 (layer 2): out = dinv*acc                    -> g_feat (final agg2)
__global__ __launch_bounds__(256) void k_gather(const float* __restrict__ b1, int mode) {
    int w = (blockIdx.x * 256 + threadIdx.x) >> 5;
    if (w >= NN) return;
    const int lane = threadIdx.x & 31;
    const int half = lane >> 4;
    const int f    = lane & 15;

    const float* __restrict__ in = mode ? g_agg : g_feat;
    int rs = g_rows[w], re = g_rows[w + 1];

    // self term counted once (half 0 only)
    float acc0 = half ? 0.0f : in[(size_t)w * NH + f];
    float acc1 = 0.0f, acc2 = 0.0f, acc3 = 0.0f;

    int c = rs;
    // 8 neighbors per iteration (4 per half), 4 independent chains
    for (; c + 8 <= re; c += 8) {
        int nb0 = __ldg(&g_csr[c     + half]);
        int nb1 = __ldg(&g_csr[c + 2 + half]);
        int nb2 = __ldg(&g_csr[c + 4 + half]);
        int nb3 = __ldg(&g_csr[c + 6 + half]);
        acc0 += in[(size_t)nb0 * NH + f];
        acc1 += in[(size_t)nb1 * NH + f];
        acc2 += in[(size_t)nb2 * NH + f];
        acc3 += in[(size_t)nb3 * NH + f];
    }
    for (; c + 4 <= re; c += 4) {
        int nb0 = __ldg(&g_csr[c + half]);
        int nb1 = __ldg(&g_csr[c + 2 + half]);
        acc0 += in[(size_t)nb0 * NH + f];
        acc1 += in[(size_t)nb1 * NH + f];
    }
    for (; c + half < re; c += 2) {
        int nb = __ldg(&g_csr[c + half]);
        acc0 += in[(size_t)nb * NH + f];
    }
    float acc = (acc0 + acc1) + (acc2 + acc3);
    acc += __shfl_down_sync(0xffffffffu, acc, 16);

    if (lane < 16) {
        float dv = g_dinv[w];
        float v = acc * dv;
        if (mode == 0) {
            v = fmaxf(v + __ldg(&b1[f]), 0.0f) * dv;
            g_agg[(size_t)w * NH + f] = v;
        } else {
            g_feat[(size_t)w * NH + f] = v;
        }
    }
}

// ---------------------------------------------------------------- out: log_softmax(agg2 @ W2 + b2)
__global__ __launch_bounds__(256) void k_out(const float* __restrict__ W2,
                                             const float* __restrict__ b2,
                                             float* __restrict__ out) {
    __shared__ float Ws[NH * NC];   // 2.5 KB
    __shared__ float bs[NC];
    int tid = threadIdx.x;
    for (int i = tid; i < NH * NC; i += 256) Ws[i] = W2[i];
    if (tid < NC) bs[tid] = b2[tid];
    __syncthreads();

    int i = blockIdx.x * 256 + tid;
    if (i >= NN) return;

    float v[NH];
    const float4* a = (const float4*)(g_feat + (size_t)i * NH);
#pragma unroll
    for (int q = 0; q < 4; q++) {
        float4 t = a[q];
        v[4*q+0] = t.x; v[4*q+1] = t.y; v[4*q+2] = t.z; v[4*q+3] = t.w;
    }

    float o[NC];
    float m = -1e30f;
#pragma unroll
    for (int k = 0; k < NC; k++) {
        float s = bs[k];
#pragma unroll
        for (int j = 0; j < NH; j++) s = fmaf(v[j], Ws[j * NC + k], s);
        o[k] = s;
        m = fmaxf(m, s);
    }
    float sum = 0.f;
#pragma unroll
    for (int k = 0; k < NC; k++) sum += __expf(o[k] - m);
    float l = m + logf(sum);

    float4* op = (float4*)(out + (size_t)i * NC);
#pragma unroll
    for (int q = 0; q < 10; q++) {
        op[q] = make_float4(o[4*q] - l, o[4*q+1] - l, o[4*q+2] - l, o[4*q+3] - l);
    }
}

// ----------------------------------------------------------------
extern "C" void kernel_launch(void* const* d_in, const int* in_sizes, int n_in,
                              void* d_out, int out_size) {
    const float* x  = (const float*)d_in[0];
    const int*   ei = (const int*)d_in[1];
    const float* W1 = (const float*)d_in[2];
    const float* b1 = (const float*)d_in[3];
    const float* W2 = (const float*)d_in[4];
    const float* b2 = (const float*)d_in[5];
    float* out = (float*)d_out;

    const int* src = ei;        // edge_index[0]
    const int* dst = ei + NE;   // edge_index[1]

    const int NB_N  = (NN + 255) / 256;        // 391
    const int NB_E4 = (NE / 4 + 255) / 256;    // 3125
    const int NB_W  = (NN * 32 + 255) / 256;   // 12500 (warp per node)

    k_zero<<<NB_N, 256>>>();
    k_deg<<<NB_E4, 256>>>(dst);
    k_scan1<<<NSB, SCB>>>();
    k_scan2<<<1, 128>>>();
    k_scan3<<<NB_N, 256>>>();
    k_fill<<<NB_E4, 256>>>(src, dst);
    k_gemm1<<<dim3((NN + 511) / 512, KCH), 256>>>(x, W1);
    k_combine<<<NB_N, 256>>>();
    k_gather<<<NB_W, 256>>>(b1, 0);   // layer 1 aggregate + relu + rescale
    k_gather<<<NB_W, 256>>>(b1, 1);   // layer 2 aggregate
    k_out<<<NB_N, 256>>>(W2, b2, out);
}

// round 15
// speedup vs baseline: 1.1710x; 1.0861x over previous
#include <cuda_runtime.h>

#define NN 100000
#define NF 512
#define NH 16
#define NC 40
#define NE 3200000
#define KCH 4            // split-K chunks
#define KC  (NF / KCH)   // 128 cols per chunk
#define SCB 1024         // scan block size
#define NSB ((NN + SCB - 1) / SCB)   // 98 scan blocks

// Scratch (no allocations allowed -> __device__ globals)
__device__ float g_dinv[NN];
__device__ float g_feat[NN * NH];       // layer-1 messages, later final agg2
__device__ float g_agg[NN * NH];        // layer-2 messages
__device__ float g_part[KCH][NN * NH];  // split-K partials (deterministic)
__device__ int   g_deg[NN];
__device__ int   g_scan[NN];            // block-local inclusive scan
__device__ int   g_rows[NN + 1];        // CSR row offsets
__device__ int   g_cursor[NN];          // fill cursors
__device__ int   g_csr[NE];             // CSR column (src) indices
__device__ int   g_bsum[NSB];
__device__ int   g_boff[NSB];

// ---------------------------------------------------------------- degree
__global__ void k_zero() {
    int i = blockIdx.x * blockDim.x + threadIdx.x;
    if (i < NN) g_deg[i] = 0;
}

// 4 edges per thread via int4 (NE % 4 == 0)
__global__ void k_deg(const int* __restrict__ dst) {
    int e4 = blockIdx.x * blockDim.x + threadIdx.x;
    if (e4 >= NE / 4) return;
    int4 d = reinterpret_cast<const int4*>(dst)[e4];
    atomicAdd(&g_deg[d.x], 1);
    atomicAdd(&g_deg[d.y], 1);
    atomicAdd(&g_deg[d.z], 1);
    atomicAdd(&g_deg[d.w], 1);
}

// ---------------------------------------------------------------- prefix scan (3 stages)
__global__ __launch_bounds__(SCB) void k_scan1() {
    __shared__ int s[SCB];
    int t = threadIdx.x;
    int i = blockIdx.x * SCB + t;
    int v = (i < NN) ? g_deg[i] : 0;
    s[t] = v;
    __syncthreads();
#pragma unroll
    for (int off = 1; off < SCB; off <<= 1) {
        int u = (t >= off) ? s[t - off] : 0;
        __syncthreads();
        s[t] += u;
        __syncthreads();
    }
    if (i < NN) g_scan[i] = s[t];
    if (t == SCB - 1) g_bsum[blockIdx.x] = s[t];
}

__global__ __launch_bounds__(128) void k_scan2() {
    __shared__ int s[128];
    int t = threadIdx.x;
    int v = (t < NSB) ? g_bsum[t] : 0;
    s[t] = v;
    __syncthreads();
#pragma unroll
    for (int off = 1; off < 128; off <<= 1) {
        int u = (t >= off) ? s[t - off] : 0;
        __syncthreads();
        s[t] += u;
        __syncthreads();
    }
    if (t < NSB) g_boff[t] = s[t] - v;   // exclusive block offsets
}

__global__ void k_scan3() {
    int i = blockIdx.x * blockDim.x + threadIdx.x;
    if (i >= NN) return;
    int d = g_deg[i];
    int excl = g_scan[i] - d + g_boff[i >> 10];
    g_rows[i] = excl;
    g_cursor[i] = excl;
    g_dinv[i] = rsqrtf((float)(d + 1));   // +1 self-loop
    if (i == 0) g_rows[NN] = NE;
}

// ---------------------------------------------------------------- CSR fill (4 edges/thread)
__global__ void k_fill(const int* __restrict__ src, const int* __restrict__ dst) {
    int e4 = blockIdx.x * blockDim.x + threadIdx.x;
    if (e4 >= NE / 4) return;
    int4 s = reinterpret_cast<const int4*>(src)[e4];
    int4 d = reinterpret_cast<const int4*>(dst)[e4];
    g_csr[atomicAdd(&g_cursor[d.x], 1)] = s.x;
    g_csr[atomicAdd(&g_cursor[d.y], 1)] = s.y;
    g_csr[atomicAdd(&g_cursor[d.z], 1)] = s.z;
    g_csr[atomicAdd(&g_cursor[d.w], 1)] = s.w;
}

// ---------------------------------------------------------------- GEMM1 (split-K, 2 nodes/thread):
// grid (196, 4), 256 threads. CTA (b,c): nodes [b*512, +512), k-cols [c*128, +128).
// W row loaded as 4x LDS.128 broadcast; each W value feeds 2 FMA2s (2 nodes).
__global__ __launch_bounds__(256) void k_gemm1(const float* __restrict__ x,
                                               const float* __restrict__ W1) {
    __shared__ __align__(16) float Ws[KC * NH];    // 8 KB
    const int tid   = threadIdx.x;
    const int chunk = blockIdx.y;
    const int n0 = blockIdx.x * 512 + tid;
    const int n1 = n0 + 256;

    for (int i = tid; i < KC * NH; i += 256) Ws[i] = W1[chunk * KC * NH + i];
    __syncthreads();
    const ulonglong2* Ws4 = reinterpret_cast<const ulonglong2*>(Ws);  // 16B granules

    const int m0 = n0 < NN ? n0 : 0;
    const int m1 = n1 < NN ? n1 : 0;
    const float4* xa = reinterpret_cast<const float4*>(x + (size_t)m0 * NF + chunk * KC);
    const float4* xb = reinterpret_cast<const float4*>(x + (size_t)m1 * NF + chunk * KC);

    unsigned long long accA[8], accB[8];
#pragma unroll
    for (int j = 0; j < 8; j++) { accA[j] = 0ull; accB[j] = 0ull; }

#pragma unroll 2
    for (int it = 0; it < KC / 8; it++) {       // 16 iters, 8 k-cols each
        float4 a0 = xa[it * 2], a1 = xa[it * 2 + 1];    // 4 batched LDG.128
        float4 b0 = xb[it * 2], b1 = xb[it * 2 + 1];
        float av[8] = {a0.x, a0.y, a0.z, a0.w, a1.x, a1.y, a1.z, a1.w};
        float bv[8] = {b0.x, b0.y, b0.z, b0.w, b1.x, b1.y, b1.z, b1.w};
#pragma unroll
        for (int c = 0; c < 8; c++) {
            const int k = it * 8 + c;
            unsigned long long a2, b2;
            asm("mov.b64 %0, {%1, %1};" : "=l"(a2) : "r"(__float_as_uint(av[c])));
            asm("mov.b64 %0, {%1, %1};" : "=l"(b2) : "r"(__float_as_uint(bv[c])));
            // W row k: 64B as 4x LDS.128 broadcast
            ulonglong2 w01 = Ws4[k * 4 + 0];
            ulonglong2 w23 = Ws4[k * 4 + 1];
            ulonglong2 w45 = Ws4[k * 4 + 2];
            ulonglong2 w67 = Ws4[k * 4 + 3];
            asm("fma.rn.f32x2 %0, %1, %2, %0;" : "+l"(accA[0]) : "l"(a2), "l"(w01.x));
            asm("fma.rn.f32x2 %0, %1, %2, %0;" : "+l"(accB[0]) : "l"(b2), "l"(w01.x));
            asm("fma.rn.f32x2 %0, %1, %2, %0;" : "+l"(accA[1]) : "l"(a2), "l"(w01.y));
            asm("fma.rn.f32x2 %0, %1, %2, %0;" : "+l"(accB[1]) : "l"(b2), "l"(w01.y));
            asm("fma.rn.f32x2 %0, %1, %2, %0;" : "+l"(accA[2]) : "l"(a2), "l"(w23.x));
            asm("fma.rn.f32x2 %0, %1, %2, %0;" : "+l"(accB[2]) : "l"(b2), "l"(w23.x));
            asm("fma.rn.f32x2 %0, %1, %2, %0;" : "+l"(accA[3]) : "l"(a2), "l"(w23.y));
            asm("fma.rn.f32x2 %0, %1, %2, %0;" : "+l"(accB[3]) : "l"(b2), "l"(w23.y));
            asm("fma.rn.f32x2 %0, %1, %2, %0;" : "+l"(accA[4]) : "l"(a2), "l"(w45.x));
            asm("fma.rn.f32x2 %0, %1, %2, %0;" : "+l"(accB[4]) : "l"(b2), "l"(w45.x));
            asm("fma.rn.f32x2 %0, %1, %2, %0;" : "+l"(accA[5]) : "l"(a2), "l"(w45.y));
            asm("fma.rn.f32x2 %0, %1, %2, %0;" : "+l"(accB[5]) : "l"(b2), "l"(w45.y));
            asm("fma.rn.f32x2 %0, %1, %2, %0;" : "+l"(accA[6]) : "l"(a2), "l"(w67.x));
            asm("fma.rn.f32x2 %0, %1, %2, %0;" : "+l"(accB[6]) : "l"(b2), "l"(w67.x));
            asm("fma.rn.f32x2 %0, %1, %2, %0;" : "+l"(accA[7]) : "l"(a2), "l"(w67.y));
            asm("fma.rn.f32x2 %0, %1, %2, %0;" : "+l"(accB[7]) : "l"(b2), "l"(w67.y));
        }
    }

#pragma unroll
    for (int half = 0; half < 2; half++) {
        int node = half ? n1 : n0;
        if (node >= NN) continue;
        unsigned long long* acc = half ? accB : accA;
        float4* p = (float4*)(&g_part[chunk][(size_t)node * NH]);
#pragma unroll
        for (int q = 0; q < 4; q++) {
            unsigned lo0, hi0, lo1, hi1;
            asm("mov.b64 {%0, %1}, %2;" : "=r"(lo0), "=r"(hi0) : "l"(acc[2*q]));
            asm("mov.b64 {%0, %1}, %2;" : "=r"(lo1), "=r"(hi1) : "l"(acc[2*q+1]));
            p[q] = make_float4(__uint_as_float(lo0), __uint_as_float(hi0),
                               __uint_as_float(lo1), __uint_as_float(hi1));
        }
    }
}

// ---------------------------------------------------------------- combine: feat = (sum parts) * dinv
__global__ void k_combine() {
    int i = blockIdx.x * blockDim.x + threadIdx.x;
    if (i >= NN) return;
    float dv = g_dinv[i];
    const float4* p0 = (const float4*)(&g_part[0][(size_t)i * NH]);
    const float4* p1 = (const float4*)(&g_part[1][(size_t)i * NH]);
    const float4* p2 = (const float4*)(&g_part[2][(size_t)i * NH]);
    const float4* p3 = (const float4*)(&g_part[3][(size_t)i * NH]);
    float4* f = (float4*)(g_feat + (size_t)i * NH);
#pragma unroll
    for (int q = 0; q < 4; q++) {
        float4 s0 = p0[q], s1 = p1[q], s2 = p2[q], s3 = p3[q];
        float4 v;
        v.x = ((s0.x + s1.x) + (s2.x + s3.x)) * dv;
        v.y = ((s0.y + s1.y) + (s2.y + s3.y)) * dv;
        v.z = ((s0.z + s1.z) + (s2.z + s3.z)) * dv;
        v.w = ((s0.w + s1.w) + (s2.w + s3.w)) * dv;
        f[q] = v;
    }
}

// ---------------------------------------------------------------- CSR gather (warp per node)
// 16 lanes per neighbor: lane (half, f) reads in[nb*16+f] (64B coalesced per
// half-warp). 4 independent accumulator chains (8 neighbors in flight/warp).
// mode 0 (layer 1): out = relu(dinv*acc + b1) * dinv  -> g_agg (layer-2 msgs)
// mode 1 (layer 2): out = dinv*acc                    -> g_feat (final agg2)
__global__ __launch_bounds__(256) void k_gather(const float* __restrict__ b1, int mode) {
    int w = (blockIdx.x * 256 + threadIdx.x) >> 5;
    if (w >= NN) return;
    const int lane = threadIdx.x & 31;
    const int half = lane >> 4;
    const int f    = lane & 15;

    const float* __restrict__ in = mode ? g_agg : g_feat;
    int rs = g_rows[w], re = g_rows[w + 1];

    // self term counted once (half 0 only)
    float acc0 = half ? 0.0f : in[(size_t)w * NH + f];
    float acc1 = 0.0f, acc2 = 0.0f, acc3 = 0.0f;

    int c = rs;
    // 8 neighbors per iteration (4 per half), 4 independent chains
    for (; c + 8 <= re; c += 8) {
        int nb0 = __ldg(&g_csr[c     + half]);
        int nb1 = __ldg(&g_csr[c + 2 + half]);
        int nb2 = __ldg(&g_csr[c + 4 + half]);
        int nb3 = __ldg(&g_csr[c + 6 + half]);
        acc0 += in[(size_t)nb0 * NH + f];
        acc1 += in[(size_t)nb1 * NH + f];
        acc2 += in[(size_t)nb2 * NH + f];
        acc3 += in[(size_t)nb3 * NH + f];
    }
    for (; c + 4 <= re; c += 4) {
        int nb0 = __ldg(&g_csr[c + half]);
        int nb1 = __ldg(&g_csr[c + 2 + half]);
        acc0 += in[(size_t)nb0 * NH + f];
        acc1 += in[(size_t)nb1 * NH + f];
    }
    for (; c + half < re; c += 2) {
        int nb = __ldg(&g_csr[c + half]);
        acc0 += in[(size_t)nb * NH + f];
    }
    float acc = (acc0 + acc1) + (acc2 + acc3);
    acc += __shfl_down_sync(0xffffffffu, acc, 16);

    if (lane < 16) {
        float dv = g_dinv[w];
        float v = acc * dv;
        if (mode == 0) {
            v = fmaxf(v + __ldg(&b1[f]), 0.0f) * dv;
            g_agg[(size_t)w * NH + f] = v;
        } else {
            g_feat[(size_t)w * NH + f] = v;
        }
    }
}

// ---------------------------------------------------------------- out: log_softmax(agg2 @ W2 + b2)
__global__ __launch_bounds__(256) void k_out(const float* __restrict__ W2,
                                             const float* __restrict__ b2,
                                             float* __restrict__ out) {
    __shared__ float Ws[NH * NC];   // 2.5 KB
    __shared__ float bs[NC];
    int tid = threadIdx.x;
    for (int i = tid; i < NH * NC; i += 256) Ws[i] = W2[i];
    if (tid < NC) bs[tid] = b2[tid];
    __syncthreads();

    int i = blockIdx.x * 256 + tid;
    if (i >= NN) return;

    float v[NH];
    const float4* a = (const float4*)(g_feat + (size_t)i * NH);
#pragma unroll
    for (int q = 0; q < 4; q++) {
        float4 t = a[q];
        v[4*q+0] = t.x; v[4*q+1] = t.y; v[4*q+2] = t.z; v[4*q+3] = t.w;
    }

    float o[NC];
    float m = -1e30f;
#pragma unroll
    for (int k = 0; k < NC; k++) {
        float s = bs[k];
#pragma unroll
        for (int j = 0; j < NH; j++) s = fmaf(v[j], Ws[j * NC + k], s);
        o[k] = s;
        m = fmaxf(m, s);
    }
    float sum = 0.f;
#pragma unroll
    for (int k = 0; k < NC; k++) sum += __expf(o[k] - m);
    float l = m + logf(sum);

    float4* op = (float4*)(out + (size_t)i * NC);
#pragma unroll
    for (int q = 0; q < 10; q++) {
        op[q] = make_float4(o[4*q] - l, o[4*q+1] - l, o[4*q+2] - l, o[4*q+3] - l);
    }
}

// ----------------------------------------------------------------
// Fork/join stream overlap: CSR build (main stream) || gemm1 (side stream).
// Stream + events are host-side resources created once (no device memory);
// the device work enqueued per call is identical and deterministic.
static cudaStream_t s_side = 0;
static cudaEvent_t  ev_fork = 0, ev_join = 0;

extern "C" void kernel_launch(void* const* d_in, const int* in_sizes, int n_in,
                              void* d_out, int out_size) {
    const float* x  = (const float*)d_in[0];
    const int*   ei = (const int*)d_in[1];
    const float* W1 = (const float*)d_in[2];
    const float* b1 = (const float*)d_in[3];
    const float* W2 = (const float*)d_in[4];
    const float* b2 = (const float*)d_in[5];
    float* out = (float*)d_out;

    const int* src = ei;        // edge_index[0]
    const int* dst = ei + NE;   // edge_index[1]

    const int NB_N  = (NN + 255) / 256;        // 391
    const int NB_E4 = (NE / 4 + 255) / 256;    // 3125
    const int NB_W  = (NN * 32 + 255) / 256;   // 12500 (warp per node)

    if (!s_side) {
        cudaStreamCreateWithFlags(&s_side, cudaStreamNonBlocking);
        cudaEventCreateWithFlags(&ev_fork, cudaEventDisableTiming);
        cudaEventCreateWithFlags(&ev_join, cudaEventDisableTiming);
    }

    // fork: side stream inherits capture dependency from the main stream
    cudaEventRecord(ev_fork, 0);
    cudaStreamWaitEvent(s_side, ev_fork, 0);

    // side chain: dense linear transform (independent of edge data)
    k_gemm1<<<dim3((NN + 511) / 512, KCH), 256, 0, s_side>>>(x, W1);
    cudaEventRecord(ev_join, s_side);

    // main chain: CSR build
    k_zero<<<NB_N, 256>>>();
    k_deg<<<NB_E4, 256>>>(dst);
    k_scan1<<<NSB, SCB>>>();
    k_scan2<<<1, 128>>>();
    k_scan3<<<NB_N, 256>>>();
    k_fill<<<NB_E4, 256>>>(src, dst);

    // join: combine needs gemm1 partials + dinv (scan3)
    cudaStreamWaitEvent(0, ev_join, 0);

    k_combine<<<NB_N, 256>>>();
    k_gather<<<NB_W, 256>>>(b1, 0);   // layer 1 aggregate + relu + rescale
    k_gather<<<NB_W, 256>>>(b1, 1);   // layer 2 aggregate
    k_out<<<NB_N, 256>>>(W2, b2, out);
}

// round 16
// speedup vs baseline: 1.2092x; 1.0327x over previous
#include <cuda_runtime.h>

#define NN 100000
#define NF 512
#define NH 16
#define NC 40
#define NE 3200000
#define KCH 4            // split-K chunks
#define KC  (NF / KCH)   // 128 cols per chunk
#define SCB 1024         // scan block size
#define NSB ((NN + SCB - 1) / SCB)   // 98 scan blocks

// Scratch (no allocations allowed -> __device__ globals)
__device__ float g_dinv[NN];
__device__ float g_feat[NN * NH];       // layer-1 messages, later final agg2
__device__ float g_agg[NN * NH];        // layer-2 messages
__device__ float g_part[KCH][NN * NH];  // split-K partials (deterministic)
__device__ int   g_deg[NN];
__device__ int   g_scan[NN];            // block-local inclusive scan
__device__ int   g_rows[NN + 1];        // CSR row offsets
__device__ int   g_cursor[NN];          // fill cursors
__device__ int   g_csr[NE];             // CSR column (src) indices
__device__ int   g_bsum[NSB];

// ---------------------------------------------------------------- degree
__global__ void k_zero() {
    int i = blockIdx.x * blockDim.x + threadIdx.x;
    if (i < NN) g_deg[i] = 0;
}

// 4 edges per thread via int4 (NE % 4 == 0)
__global__ void k_deg(const int* __restrict__ dst) {
    int e4 = blockIdx.x * blockDim.x + threadIdx.x;
    if (e4 >= NE / 4) return;
    int4 d = reinterpret_cast<const int4*>(dst)[e4];
    atomicAdd(&g_deg[d.x], 1);
    atomicAdd(&g_deg[d.y], 1);
    atomicAdd(&g_deg[d.z], 1);
    atomicAdd(&g_deg[d.w], 1);
}

// ---------------------------------------------------------------- prefix scan (2 stages)
__global__ __launch_bounds__(SCB) void k_scan1() {
    __shared__ int s[SCB];
    int t = threadIdx.x;
    int i = blockIdx.x * SCB + t;
    int v = (i < NN) ? g_deg[i] : 0;
    s[t] = v;
    __syncthreads();
#pragma unroll
    for (int off = 1; off < SCB; off <<= 1) {
        int u = (t >= off) ? s[t - off] : 0;
        __syncthreads();
        s[t] += u;
        __syncthreads();
    }
    if (i < NN) g_scan[i] = s[t];
    if (t == SCB - 1) g_bsum[blockIdx.x] = s[t];
}

// scan3: each block recomputes the 98-entry block-sum prefix locally (cheap),
// then emits rows/cursor/dinv. Eliminates the separate scan2 launch.
__global__ __launch_bounds__(256) void k_scan3() {
    __shared__ int s[128];
    __shared__ int boffs[128];
    int t = threadIdx.x;
    int orig = 0;
    if (t < 128) {
        orig = (t < NSB) ? g_bsum[t] : 0;
        s[t] = orig;
    }
    __syncthreads();
#pragma unroll
    for (int off = 1; off < 128; off <<= 1) {
        int u = 0;
        if (t < 128 && t >= off) u = s[t - off];
        __syncthreads();
        if (t < 128) s[t] += u;
        __syncthreads();
    }
    if (t < 128) boffs[t] = s[t] - orig;   // exclusive prefix
    __syncthreads();

    int i = blockIdx.x * 256 + t;
    if (i >= NN) return;
    int d = g_deg[i];
    int excl = g_scan[i] - d + boffs[i >> 10];
    g_rows[i] = excl;
    g_cursor[i] = excl;
    g_dinv[i] = rsqrtf((float)(d + 1));   // +1 self-loop
    if (i == 0) g_rows[NN] = NE;
}

// ---------------------------------------------------------------- CSR fill (4 edges/thread)
__global__ void k_fill(const int* __restrict__ src, const int* __restrict__ dst) {
    int e4 = blockIdx.x * blockDim.x + threadIdx.x;
    if (e4 >= NE / 4) return;
    int4 s = reinterpret_cast<const int4*>(src)[e4];
    int4 d = reinterpret_cast<const int4*>(dst)[e4];
    g_csr[atomicAdd(&g_cursor[d.x], 1)] = s.x;
    g_csr[atomicAdd(&g_cursor[d.y], 1)] = s.y;
    g_csr[atomicAdd(&g_cursor[d.z], 1)] = s.z;
    g_csr[atomicAdd(&g_cursor[d.w], 1)] = s.w;
}

// ---------------------------------------------------------------- GEMM1 (split-K, 2 nodes/thread):
// grid (196, 4), 256 threads. W row loaded as 4x LDS.128 broadcast; each W
// value feeds 2 FMA2s (2 nodes).
__global__ __launch_bounds__(256) void k_gemm1(const float* __restrict__ x,
                                               const float* __restrict__ W1) {
    __shared__ __align__(16) float Ws[KC * NH];    // 8 KB
    const int tid   = threadIdx.x;
    const int chunk = blockIdx.y;
    const int n0 = blockIdx.x * 512 + tid;
    const int n1 = n0 + 256;

    for (int i = tid; i < KC * NH; i += 256) Ws[i] = W1[chunk * KC * NH + i];
    __syncthreads();
    const ulonglong2* Ws4 = reinterpret_cast<const ulonglong2*>(Ws);  // 16B granules

    const int m0 = n0 < NN ? n0 : 0;
    const int m1 = n1 < NN ? n1 : 0;
    const float4* xa = reinterpret_cast<const float4*>(x + (size_t)m0 * NF + chunk * KC);
    const float4* xb = reinterpret_cast<const float4*>(x + (size_t)m1 * NF + chunk * KC);

    unsigned long long accA[8], accB[8];
#pragma unroll
    for (int j = 0; j < 8; j++) { accA[j] = 0ull; accB[j] = 0ull; }

#pragma unroll 2
    for (int it = 0; it < KC / 8; it++) {       // 16 iters, 8 k-cols each
        float4 a0 = xa[it * 2], a1 = xa[it * 2 + 1];    // 4 batched LDG.128
        float4 b0 = xb[it * 2], b1 = xb[it * 2 + 1];
        float av[8] = {a0.x, a0.y, a0.z, a0.w, a1.x, a1.y, a1.z, a1.w};
        float bv[8] = {b0.x, b0.y, b0.z, b0.w, b1.x, b1.y, b1.z, b1.w};
#pragma unroll
        for (int c = 0; c < 8; c++) {
            const int k = it * 8 + c;
            unsigned long long a2, b2;
            asm("mov.b64 %0, {%1, %1};" : "=l"(a2) : "r"(__float_as_uint(av[c])));
            asm("mov.b64 %0, {%1, %1};" : "=l"(b2) : "r"(__float_as_uint(bv[c])));
            // W row k: 64B as 4x LDS.128 broadcast
            ulonglong2 w01 = Ws4[k * 4 + 0];
            ulonglong2 w23 = Ws4[k * 4 + 1];
            ulonglong2 w45 = Ws4[k * 4 + 2];
            ulonglong2 w67 = Ws4[k * 4 + 3];
            asm("fma.rn.f32x2 %0, %1, %2, %0;" : "+l"(accA[0]) : "l"(a2), "l"(w01.x));
            asm("fma.rn.f32x2 %0, %1, %2, %0;" : "+l"(accB[0]) : "l"(b2), "l"(w01.x));
            asm("fma.rn.f32x2 %0, %1, %2, %0;" : "+l"(accA[1]) : "l"(a2), "l"(w01.y));
            asm("fma.rn.f32x2 %0, %1, %2, %0;" : "+l"(accB[1]) : "l"(b2), "l"(w01.y));
            asm("fma.rn.f32x2 %0, %1, %2, %0;" : "+l"(accA[2]) : "l"(a2), "l"(w23.x));
            asm("fma.rn.f32x2 %0, %1, %2, %0;" : "+l"(accB[2]) : "l"(b2), "l"(w23.x));
            asm("fma.rn.f32x2 %0, %1, %2, %0;" : "+l"(accA[3]) : "l"(a2), "l"(w23.y));
            asm("fma.rn.f32x2 %0, %1, %2, %0;" : "+l"(accB[3]) : "l"(b2), "l"(w23.y));
            asm("fma.rn.f32x2 %0, %1, %2, %0;" : "+l"(accA[4]) : "l"(a2), "l"(w45.x));
            asm("fma.rn.f32x2 %0, %1, %2, %0;" : "+l"(accB[4]) : "l"(b2), "l"(w45.x));
            asm("fma.rn.f32x2 %0, %1, %2, %0;" : "+l"(accA[5]) : "l"(a2), "l"(w45.y));
            asm("fma.rn.f32x2 %0, %1, %2, %0;" : "+l"(accB[5]) : "l"(b2), "l"(w45.y));
            asm("fma.rn.f32x2 %0, %1, %2, %0;" : "+l"(accA[6]) : "l"(a2), "l"(w67.x));
            asm("fma.rn.f32x2 %0, %1, %2, %0;" : "+l"(accB[6]) : "l"(b2), "l"(w67.x));
            asm("fma.rn.f32x2 %0, %1, %2, %0;" : "+l"(accA[7]) : "l"(a2), "l"(w67.y));
            asm("fma.rn.f32x2 %0, %1, %2, %0;" : "+l"(accB[7]) : "l"(b2), "l"(w67.y));
        }
    }

#pragma unroll
    for (int half = 0; half < 2; half++) {
        int node = half ? n1 : n0;
        if (node >= NN) continue;
        unsigned long long* acc = half ? accB : accA;
        float4* p = (float4*)(&g_part[chunk][(size_t)node * NH]);
#pragma unroll
        for (int q = 0; q < 4; q++) {
            unsigned lo0, hi0, lo1, hi1;
            asm("mov.b64 {%0, %1}, %2;" : "=r"(lo0), "=r"(hi0) : "l"(acc[2*q]));
            asm("mov.b64 {%0, %1}, %2;" : "=r"(lo1), "=r"(hi1) : "l"(acc[2*q+1]));
            p[q] = make_float4(__uint_as_float(lo0), __uint_as_float(hi0),
                               __uint_as_float(lo1), __uint_as_float(hi1));
        }
    }
}

// ---------------------------------------------------------------- combine: feat = (sum parts) * dinv
__global__ void k_combine() {
    int i = blockIdx.x * blockDim.x + threadIdx.x;
    if (i >= NN) return;
    float dv = g_dinv[i];
    const float4* p0 = (const float4*)(&g_part[0][(size_t)i * NH]);
    const float4* p1 = (const float4*)(&g_part[1][(size_t)i * NH]);
    const float4* p2 = (const float4*)(&g_part[2][(size_t)i * NH]);
    const float4* p3 = (const float4*)(&g_part[3][(size_t)i * NH]);
    float4* f = (float4*)(g_feat + (size_t)i * NH);
#pragma unroll
    for (int q = 0; q < 4; q++) {
        float4 s0 = p0[q], s1 = p1[q], s2 = p2[q], s3 = p3[q];
        float4 v;
        v.x = ((s0.x + s1.x) + (s2.x + s3.x)) * dv;
        v.y = ((s0.y + s1.y) + (s2.y + s3.y)) * dv;
        v.z = ((s0.z + s1.z) + (s2.z + s3.z)) * dv;
        v.w = ((s0.w + s1.w) + (s2.w + s3.w)) * dv;
        f[q] = v;
    }
}

// ---------------------------------------------------------------- CSR gather (warp per node)
// 16 lanes per neighbor: lane (half, f) reads in[nb*16+f] (64B coalesced per
// half-warp). 8 independent accumulator chains (16 neighbors in flight/warp).
// mode 0 (layer 1): out = relu(dinv*acc + b1) * dinv  -> g_agg (layer-2 msgs)
// mode 1 (layer 2): out = dinv*acc                    -> g_feat (final agg2)
__global__ __launch_bounds__(256) void k_gather(const float* __restrict__ b1, int mode) {
    int w = (blockIdx.x * 256 + threadIdx.x) >> 5;
    if (w >= NN) return;
    const int lane = threadIdx.x & 31;
    const int half = lane >> 4;
    const int f    = lane & 15;

    const float* __restrict__ in = mode ? g_agg : g_feat;
    int rs = g_rows[w], re = g_rows[w + 1];

    float acc[8];
    acc[0] = half ? 0.0f : in[(size_t)w * NH + f];   // self term once
#pragma unroll
    for (int j = 1; j < 8; j++) acc[j] = 0.0f;

    int c = rs;
    // 16 neighbors per iteration (8 per half), 8 independent chains
    for (; c + 16 <= re; c += 16) {
        int nb[8];
#pragma unroll
        for (int j = 0; j < 8; j++) nb[j] = __ldg(&g_csr[c + 2 * j + half]);
#pragma unroll
        for (int j = 0; j < 8; j++) acc[j] += in[(size_t)nb[j] * NH + f];
    }
    for (; c + 8 <= re; c += 8) {
        int nb0 = __ldg(&g_csr[c     + half]);
        int nb1 = __ldg(&g_csr[c + 2 + half]);
        int nb2 = __ldg(&g_csr[c + 4 + half]);
        int nb3 = __ldg(&g_csr[c + 6 + half]);
        acc[0] += in[(size_t)nb0 * NH + f];
        acc[1] += in[(size_t)nb1 * NH + f];
        acc[2] += in[(size_t)nb2 * NH + f];
        acc[3] += in[(size_t)nb3 * NH + f];
    }
    for (; c + 4 <= re; c += 4) {
        int nb0 = __ldg(&g_csr[c + half]);
        int nb1 = __ldg(&g_csr[c + 2 + half]);
        acc[0] += in[(size_t)nb0 * NH + f];
        acc[1] += in[(size_t)nb1 * NH + f];
    }
    for (; c + half < re; c += 2) {
        int nb = __ldg(&g_csr[c + half]);
        acc[0] += in[(size_t)nb * NH + f];
    }
    float a = ((acc[0] + acc[1]) + (acc[2] + acc[3]))
            + ((acc[4] + acc[5]) + (acc[6] + acc[7]));
    a += __shfl_down_sync(0xffffffffu, a, 16);

    if (lane < 16) {
        float dv = g_dinv[w];
        float v = a * dv;
        if (mode == 0) {
            v = fmaxf(v + __ldg(&b1[f]), 0.0f) * dv;
            g_agg[(size_t)w * NH + f] = v;
        } else {
            g_feat[(size_t)w * NH + f] = v;
        }
    }
}

// ---------------------------------------------------------------- out: log_softmax(agg2 @ W2 + b2)
__global__ __launch_bounds__(256) void k_out(const float* __restrict__ W2,
                                             const float* __restrict__ b2,
                                             float* __restrict__ out) {
    __shared__ float Ws[NH * NC];   // 2.5 KB
    __shared__ float bs[NC];
    int tid = threadIdx.x;
    for (int i = tid; i < NH * NC; i += 256) Ws[i] = W2[i];
    if (tid < NC) bs[tid] = b2[tid];
    __syncthreads();

    int i = blockIdx.x * 256 + tid;
    if (i >= NN) return;

    float v[NH];
    const float4* a = (const float4*)(g_feat + (size_t)i * NH);
#pragma unroll
    for (int q = 0; q < 4; q++) {
        float4 t = a[q];
        v[4*q+0] = t.x; v[4*q+1] = t.y; v[4*q+2] = t.z; v[4*q+3] = t.w;
    }

    float o[NC];
    float m = -1e30f;
#pragma unroll
    for (int k = 0; k < NC; k++) {
        float s = bs[k];
#pragma unroll
        for (int j = 0; j < NH; j++) s = fmaf(v[j], Ws[j * NC + k], s);
        o[k] = s;
        m = fmaxf(m, s);
    }
    float sum = 0.f;
#pragma unroll
    for (int k = 0; k < NC; k++) sum += __expf(o[k] - m);
    float l = m + logf(sum);

    float4* op = (float4*)(out + (size_t)i * NC);
#pragma unroll
    for (int q = 0; q < 10; q++) {
        op[q] = make_float4(o[4*q] - l, o[4*q+1] - l, o[4*q+2] - l, o[4*q+3] - l);
    }
}

// ----------------------------------------------------------------
// Fork/join stream overlap:
//   main:  zero -> deg -> scan1 -> scan3 -> fill
//   side:  gemm1 || (waits scan3) combine       (combine overlaps with fill)
// join before gathers. Stream + events are host-side resources created once.
static cudaStream_t s_side = 0;
static cudaEvent_t  ev_fork = 0, ev_scan3 = 0, ev_join = 0;

extern "C" void kernel_launch(void* const* d_in, const int* in_sizes, int n_in,
                              void* d_out, int out_size) {
    const float* x  = (const float*)d_in[0];
    const int*   ei = (const int*)d_in[1];
    const float* W1 = (const float*)d_in[2];
    const float* b1 = (const float*)d_in[3];
    const float* W2 = (const float*)d_in[4];
    const float* b2 = (const float*)d_in[5];
    float* out = (float*)d_out;

    const int* src = ei;        // edge_index[0]
    const int* dst = ei + NE;   // edge_index[1]

    const int NB_N  = (NN + 255) / 256;        // 391
    const int NB_E4 = (NE / 4 + 255) / 256;    // 3125
    const int NB_W  = (NN * 32 + 255) / 256;   // 12500 (warp per node)

    if (!s_side) {
        cudaStreamCreateWithFlags(&s_side, cudaStreamNonBlocking);
        cudaEventCreateWithFlags(&ev_fork, cudaEventDisableTiming);
        cudaEventCreateWithFlags(&ev_scan3, cudaEventDisableTiming);
        cudaEventCreateWithFlags(&ev_join, cudaEventDisableTiming);
    }

    // fork: side stream inherits capture dependency from the main stream
    cudaEventRecord(ev_fork, 0);
    cudaStreamWaitEvent(s_side, ev_fork, 0);

    // side chain: dense linear transform (independent of edge data)
    k_gemm1<<<dim3((NN + 511) / 512, KCH), 256, 0, s_side>>>(x, W1);

    // main chain: CSR build
    k_zero<<<NB_N, 256>>>();
    k_deg<<<NB_E4, 256>>>(dst);
    k_scan1<<<NSB, SCB>>>();
    k_scan3<<<NB_N, 256>>>();
    cudaEventRecord(ev_scan3, 0);
    k_fill<<<NB_E4, 256>>>(src, dst);

    // side: combine (needs gemm1 partials + dinv from scan3); overlaps fill
    cudaStreamWaitEvent(s_side, ev_scan3, 0);
    k_combine<<<NB_N, 256, 0, s_side>>>();
    cudaEventRecord(ev_join, s_side);

    // join: gathers need CSR (main) + feat (side)
    cudaStreamWaitEvent(0, ev_join, 0);

    k_gather<<<NB_W, 256>>>(b1, 0);   // layer 1 aggregate + relu + rescale
    k_gather<<<NB_W, 256>>>(b1, 1);   // layer 2 aggregate
    k_out<<<NB_N, 256>>>(W2, b2, out);
}

// round 17
// speedup vs baseline: 1.3159x; 1.0883x over previous
#include <cuda_runtime.h>

#define NN 100000
#define NF 512
#define NH 16
#define NC 40
#define NE 3200000
#define KCH 4            // split-K chunks
#define KC  (NF / KCH)   // 128 cols per chunk
#define SCB 1024         // scan block size
#define NSB ((NN + SCB - 1) / SCB)   // 98 scan blocks

#define ADD2(o, a, b) asm("add.rn.f32x2 %0, %1, %2;" : "=l"(o) : "l"(a), "l"(b))

// Scratch (no allocations allowed -> __device__ globals)
__device__ float g_dinv[NN];
__device__ float g_feat[NN * NH];       // layer-1 messages, later final agg2
__device__ float g_agg[NN * NH];        // layer-2 messages
__device__ float g_part[KCH][NN * NH];  // split-K partials (deterministic)
__device__ int   g_deg[NN];
__device__ int   g_scan[NN];            // block-local inclusive scan
__device__ int   g_rows[NN + 1];        // CSR row offsets
__device__ int   g_cursor[NN];          // fill cursors
__device__ int   g_csr[NE];             // CSR column (src) indices
__device__ int   g_bsum[NSB];

// ---------------------------------------------------------------- degree
__global__ void k_zero() {
    int i = blockIdx.x * blockDim.x + threadIdx.x;
    if (i < NN) g_deg[i] = 0;
}

// 4 edges per thread via int4 (NE % 4 == 0)
__global__ void k_deg(const int* __restrict__ dst) {
    int e4 = blockIdx.x * blockDim.x + threadIdx.x;
    if (e4 >= NE / 4) return;
    int4 d = reinterpret_cast<const int4*>(dst)[e4];
    atomicAdd(&g_deg[d.x], 1);
    atomicAdd(&g_deg[d.y], 1);
    atomicAdd(&g_deg[d.z], 1);
    atomicAdd(&g_deg[d.w], 1);
}

// ---------------------------------------------------------------- prefix scan (2 stages)
__global__ __launch_bounds__(SCB) void k_scan1() {
    __shared__ int s[SCB];
    int t = threadIdx.x;
    int i = blockIdx.x * SCB + t;
    int v = (i < NN) ? g_deg[i] : 0;
    s[t] = v;
    __syncthreads();
#pragma unroll
    for (int off = 1; off < SCB; off <<= 1) {
        int u = (t >= off) ? s[t - off] : 0;
        __syncthreads();
        s[t] += u;
        __syncthreads();
    }
    if (i < NN) g_scan[i] = s[t];
    if (t == SCB - 1) g_bsum[blockIdx.x] = s[t];
}

// scan3: each block recomputes the 98-entry block-sum prefix locally (cheap),
// then emits rows/cursor/dinv. Eliminates the separate scan2 launch.
__global__ __launch_bounds__(256) void k_scan3() {
    __shared__ int s[128];
    __shared__ int boffs[128];
    int t = threadIdx.x;
    int orig = 0;
    if (t < 128) {
        orig = (t < NSB) ? g_bsum[t] : 0;
        s[t] = orig;
    }
    __syncthreads();
#pragma unroll
    for (int off = 1; off < 128; off <<= 1) {
        int u = 0;
        if (t < 128 && t >= off) u = s[t - off];
        __syncthreads();
        if (t < 128) s[t] += u;
        __syncthreads();
    }
    if (t < 128) boffs[t] = s[t] - orig;   // exclusive prefix
    __syncthreads();

    int i = blockIdx.x * 256 + t;
    if (i >= NN) return;
    int d = g_deg[i];
    int excl = g_scan[i] - d + boffs[i >> 10];
    g_rows[i] = excl;
    g_cursor[i] = excl;
    g_dinv[i] = rsqrtf((float)(d + 1));   // +1 self-loop
    if (i == 0) g_rows[NN] = NE;
}

// ---------------------------------------------------------------- CSR fill (4 edges/thread)
__global__ void k_fill(const int* __restrict__ src, const int* __restrict__ dst) {
    int e4 = blockIdx.x * blockDim.x + threadIdx.x;
    if (e4 >= NE / 4) return;
    int4 s = reinterpret_cast<const int4*>(src)[e4];
    int4 d = reinterpret_cast<const int4*>(dst)[e4];
    g_csr[atomicAdd(&g_cursor[d.x], 1)] = s.x;
    g_csr[atomicAdd(&g_cursor[d.y], 1)] = s.y;
    g_csr[atomicAdd(&g_cursor[d.z], 1)] = s.z;
    g_csr[atomicAdd(&g_cursor[d.w], 1)] = s.w;
}

// ---------------------------------------------------------------- GEMM1 (split-K, 2 nodes/thread):
// grid (196, 4), 256 threads. W row loaded as 4x LDS.128 broadcast; each W
// value feeds 2 FMA2s (2 nodes).
__global__ __launch_bounds__(256) void k_gemm1(const float* __restrict__ x,
                                               const float* __restrict__ W1) {
    __shared__ __align__(16) float Ws[KC * NH];    // 8 KB
    const int tid   = threadIdx.x;
    const int chunk = blockIdx.y;
    const int n0 = blockIdx.x * 512 + tid;
    const int n1 = n0 + 256;

    for (int i = tid; i < KC * NH; i += 256) Ws[i] = W1[chunk * KC * NH + i];
    __syncthreads();
    const ulonglong2* Ws4 = reinterpret_cast<const ulonglong2*>(Ws);  // 16B granules

    const int m0 = n0 < NN ? n0 : 0;
    const int m1 = n1 < NN ? n1 : 0;
    const float4* xa = reinterpret_cast<const float4*>(x + (size_t)m0 * NF + chunk * KC);
    const float4* xb = reinterpret_cast<const float4*>(x + (size_t)m1 * NF + chunk * KC);

    unsigned long long accA[8], accB[8];
#pragma unroll
    for (int j = 0; j < 8; j++) { accA[j] = 0ull; accB[j] = 0ull; }

#pragma unroll 2
    for (int it = 0; it < KC / 8; it++) {       // 16 iters, 8 k-cols each
        float4 a0 = xa[it * 2], a1 = xa[it * 2 + 1];    // 4 batched LDG.128
        float4 b0 = xb[it * 2], b1 = xb[it * 2 + 1];
        float av[8] = {a0.x, a0.y, a0.z, a0.w, a1.x, a1.y, a1.z, a1.w};
        float bv[8] = {b0.x, b0.y, b0.z, b0.w, b1.x, b1.y, b1.z, b1.w};
#pragma unroll
        for (int c = 0; c < 8; c++) {
            const int k = it * 8 + c;
            unsigned long long a2, b2;
            asm("mov.b64 %0, {%1, %1};" : "=l"(a2) : "r"(__float_as_uint(av[c])));
            asm("mov.b64 %0, {%1, %1};" : "=l"(b2) : "r"(__float_as_uint(bv[c])));
            // W row k: 64B as 4x LDS.128 broadcast
            ulonglong2 w01 = Ws4[k * 4 + 0];
            ulonglong2 w23 = Ws4[k * 4 + 1];
            ulonglong2 w45 = Ws4[k * 4 + 2];
            ulonglong2 w67 = Ws4[k * 4 + 3];
            asm("fma.rn.f32x2 %0, %1, %2, %0;" : "+l"(accA[0]) : "l"(a2), "l"(w01.x));
            asm("fma.rn.f32x2 %0, %1, %2, %0;" : "+l"(accB[0]) : "l"(b2), "l"(w01.x));
            asm("fma.rn.f32x2 %0, %1, %2, %0;" : "+l"(accA[1]) : "l"(a2), "l"(w01.y));
            asm("fma.rn.f32x2 %0, %1, %2, %0;" : "+l"(accB[1]) : "l"(b2), "l"(w01.y));
            asm("fma.rn.f32x2 %0, %1, %2, %0;" : "+l"(accA[2]) : "l"(a2), "l"(w23.x));
            asm("fma.rn.f32x2 %0, %1, %2, %0;" : "+l"(accB[2]) : "l"(b2), "l"(w23.x));
            asm("fma.rn.f32x2 %0, %1, %2, %0;" : "+l"(accA[3]) : "l"(a2), "l"(w23.y));
            asm("fma.rn.f32x2 %0, %1, %2, %0;" : "+l"(accB[3]) : "l"(b2), "l"(w23.y));
            asm("fma.rn.f32x2 %0, %1, %2, %0;" : "+l"(accA[4]) : "l"(a2), "l"(w45.x));
            asm("fma.rn.f32x2 %0, %1, %2, %0;" : "+l"(accB[4]) : "l"(b2), "l"(w45.x));
            asm("fma.rn.f32x2 %0, %1, %2, %0;" : "+l"(accA[5]) : "l"(a2), "l"(w45.y));
            asm("fma.rn.f32x2 %0, %1, %2, %0;" : "+l"(accB[5]) : "l"(b2), "l"(w45.y));
            asm("fma.rn.f32x2 %0, %1, %2, %0;" : "+l"(accA[6]) : "l"(a2), "l"(w67.x));
            asm("fma.rn.f32x2 %0, %1, %2, %0;" : "+l"(accB[6]) : "l"(b2), "l"(w67.x));
            asm("fma.rn.f32x2 %0, %1, %2, %0;" : "+l"(accA[7]) : "l"(a2), "l"(w67.y));
            asm("fma.rn.f32x2 %0, %1, %2, %0;" : "+l"(accB[7]) : "l"(b2), "l"(w67.y));
        }
    }

#pragma unroll
    for (int half = 0; half < 2; half++) {
        int node = half ? n1 : n0;
        if (node >= NN) continue;
        unsigned long long* acc = half ? accB : accA;
        float4* p = (float4*)(&g_part[chunk][(size_t)node * NH]);
#pragma unroll
        for (int q = 0; q < 4; q++) {
            unsigned lo0, hi0, lo1, hi1;
            asm("mov.b64 {%0, %1}, %2;" : "=r"(lo0), "=r"(hi0) : "l"(acc[2*q]));
            asm("mov.b64 {%0, %1}, %2;" : "=r"(lo1), "=r"(hi1) : "l"(acc[2*q+1]));
            p[q] = make_float4(__uint_as_float(lo0), __uint_as_float(hi0),
                               __uint_as_float(lo1), __uint_as_float(hi1));
        }
    }
}

// ---------------------------------------------------------------- combine: feat = (sum parts) * dinv
__global__ void k_combine() {
    int i = blockIdx.x * blockDim.x + threadIdx.x;
    if (i >= NN) return;
    float dv = g_dinv[i];
    const float4* p0 = (const float4*)(&g_part[0][(size_t)i * NH]);
    const float4* p1 = (const float4*)(&g_part[1][(size_t)i * NH]);
    const float4* p2 = (const float4*)(&g_part[2][(size_t)i * NH]);
    const float4* p3 = (const float4*)(&g_part[3][(size_t)i * NH]);
    float4* f = (float4*)(g_feat + (size_t)i * NH);
#pragma unroll
    for (int q = 0; q < 4; q++) {
        float4 s0 = p0[q], s1 = p1[q], s2 = p2[q], s3 = p3[q];
        float4 v;
        v.x = ((s0.x + s1.x) + (s2.x + s3.x)) * dv;
        v.y = ((s0.y + s1.y) + (s2.y + s3.y)) * dv;
        v.z = ((s0.z + s1.z) + (s2.z + s3.z)) * dv;
        v.w = ((s0.w + s1.w) + (s2.w + s3.w)) * dv;
        f[q] = v;
    }
}

// ---------------------------------------------------------------- CSR gather (4 lanes per node)
// Lane (node, sub) owns feature quad [sub*4, sub*4+4). Per neighbor: LDG.128
// of its quad, f32x2 accumulate. 4 independent chains; no cross-lane reduce.
// mode 0 (layer 1): out = relu(dinv*acc + b1) * dinv  -> g_agg (layer-2 msgs)
// mode 1 (layer 2): out = dinv*acc                    -> g_feat (final agg2)
__global__ __launch_bounds__(256) void k_gather(const float* __restrict__ b1, int mode) {
    int t = blockIdx.x * 256 + threadIdx.x;
    int w = t >> 2;
    if (w >= NN) return;
    const int sub = t & 3;

    const ulonglong2* __restrict__ in =
        reinterpret_cast<const ulonglong2*>(mode ? g_agg : g_feat);

    int rs = __ldg(&g_rows[w]), re = __ldg(&g_rows[w + 1]);

    ulonglong2 a0 = in[(size_t)w * 4 + sub];    // self term
    ulonglong2 a1, a2, a3;
    a1.x = a1.y = a2.x = a2.y = a3.x = a3.y = 0ull;

    int c = rs;
    for (; c + 4 <= re; c += 4) {
        int nb0 = __ldg(&g_csr[c + 0]);
        int nb1 = __ldg(&g_csr[c + 1]);
        int nb2 = __ldg(&g_csr[c + 2]);
        int nb3 = __ldg(&g_csr[c + 3]);
        ulonglong2 v0 = in[(size_t)nb0 * 4 + sub];
        ulonglong2 v1 = in[(size_t)nb1 * 4 + sub];
        ulonglong2 v2 = in[(size_t)nb2 * 4 + sub];
        ulonglong2 v3 = in[(size_t)nb3 * 4 + sub];
        ADD2(a0.x, a0.x, v0.x); ADD2(a0.y, a0.y, v0.y);
        ADD2(a1.x, a1.x, v1.x); ADD2(a1.y, a1.y, v1.y);
        ADD2(a2.x, a2.x, v2.x); ADD2(a2.y, a2.y, v2.y);
        ADD2(a3.x, a3.x, v3.x); ADD2(a3.y, a3.y, v3.y);
    }
    for (; c < re; c++) {
        int nb = __ldg(&g_csr[c]);
        ulonglong2 v = in[(size_t)nb * 4 + sub];
        ADD2(a0.x, a0.x, v.x); ADD2(a0.y, a0.y, v.y);
    }
    ADD2(a0.x, a0.x, a1.x); ADD2(a0.y, a0.y, a1.y);
    ADD2(a2.x, a2.x, a3.x); ADD2(a2.y, a2.y, a3.y);
    ADD2(a0.x, a0.x, a2.x); ADD2(a0.y, a0.y, a2.y);

    unsigned u0, u1, u2, u3;
    asm("mov.b64 {%0, %1}, %2;" : "=r"(u0), "=r"(u1) : "l"(a0.x));
    asm("mov.b64 {%0, %1}, %2;" : "=r"(u2), "=r"(u3) : "l"(a0.y));
    float f0 = __uint_as_float(u0), f1 = __uint_as_float(u1);
    float f2 = __uint_as_float(u2), f3 = __uint_as_float(u3);

    float dv = g_dinv[w];
    float4 o;
    if (mode == 0) {
        const float4 bb = *reinterpret_cast<const float4*>(b1 + sub * 4);
        o.x = fmaxf(fmaf(f0, dv, bb.x), 0.f) * dv;
        o.y = fmaxf(fmaf(f1, dv, bb.y), 0.f) * dv;
        o.z = fmaxf(fmaf(f2, dv, bb.z), 0.f) * dv;
        o.w = fmaxf(fmaf(f3, dv, bb.w), 0.f) * dv;
        reinterpret_cast<float4*>(g_agg)[(size_t)w * 4 + sub] = o;
    } else {
        o.x = f0 * dv; o.y = f1 * dv; o.z = f2 * dv; o.w = f3 * dv;
        reinterpret_cast<float4*>(g_feat)[(size_t)w * 4 + sub] = o;
    }
}

// ---------------------------------------------------------------- out: log_softmax(agg2 @ W2 + b2)
// exp on the FMA pipe (magic-number 2^n + degree-5 poly) -- the MUFU pipe at
// rt=8/SMSP would cost ~28us for 4M exps; this runs in ~3us of FMA time.
__device__ __forceinline__ float fast_exp(float xs) {
    float y = fmaxf(xs * 1.4426950408889634f, -120.0f);   // log2(e), clamp
    float tt = y + 12582912.0f;                           // 1.5 * 2^23
    int  n  = __float_as_int(tt) - 0x4B400000;
    float r = y - (tt - 12582912.0f);                     // r in [-0.5, 0.5]
    float p = 1.33335581e-3f;
    p = fmaf(p, r, 9.61812910e-3f);
    p = fmaf(p, r, 5.55041087e-2f);
    p = fmaf(p, r, 2.40226507e-1f);
    p = fmaf(p, r, 6.93147180e-1f);
    p = fmaf(p, r, 1.0f);
    return __int_as_float((n + 127) << 23) * p;
}

__global__ __launch_bounds__(256) void k_out(const float* __restrict__ W2,
                                             const float* __restrict__ b2,
                                             float* __restrict__ out) {
    __shared__ float Ws[NH * NC];   // 2.5 KB
    __shared__ float bs[NC];
    int tid = threadIdx.x;
    for (int i = tid; i < NH * NC; i += 256) Ws[i] = W2[i];
    if (tid < NC) bs[tid] = b2[tid];
    __syncthreads();

    int i = blockIdx.x * 256 + tid;
    if (i >= NN) return;

    float v[NH];
    const float4* a = (const float4*)(g_feat + (size_t)i * NH);
#pragma unroll
    for (int q = 0; q < 4; q++) {
        float4 t = a[q];
        v[4*q+0] = t.x; v[4*q+1] = t.y; v[4*q+2] = t.z; v[4*q+3] = t.w;
    }

    float o[NC];
    float m = -1e30f;
#pragma unroll
    for (int k = 0; k < NC; k++) {
        float s = bs[k];
#pragma unroll
        for (int j = 0; j < NH; j++) s = fmaf(v[j], Ws[j * NC + k], s);
        o[k] = s;
        m = fmaxf(m, s);
    }
    float sum = 0.f;
#pragma unroll
    for (int k = 0; k < NC; k++) sum += fast_exp(o[k] - m);
    float l = m + logf(sum);

    float4* op = (float4*)(out + (size_t)i * NC);
#pragma unroll
    for (int q = 0; q < 10; q++) {
        op[q] = make_float4(o[4*q] - l, o[4*q+1] - l, o[4*q+2] - l, o[4*q+3] - l);
    }
}

// ----------------------------------------------------------------
// Fork/join stream overlap:
//   main:  zero -> deg -> scan1 -> scan3 -> fill
//   side:  gemm1 || (waits scan3) combine       (combine overlaps with fill)
// join before gathers. Stream + events are host-side resources created once.
static cudaStream_t s_side = 0;
static cudaEvent_t  ev_fork = 0, ev_scan3 = 0, ev_join = 0;

extern "C" void kernel_launch(void* const* d_in, const int* in_sizes, int n_in,
                              void* d_out, int out_size) {
    const float* x  = (const float*)d_in[0];
    const int*   ei = (const int*)d_in[1];
    const float* W1 = (const float*)d_in[2];
    const float* b1 = (const float*)d_in[3];
    const float* W2 = (const float*)d_in[4];
    const float* b2 = (const float*)d_in[5];
    float* out = (float*)d_out;

    const int* src = ei;        // edge_index[0]
    const int* dst = ei + NE;   // edge_index[1]

    const int NB_N  = (NN + 255) / 256;        // 391
    const int NB_E4 = (NE / 4 + 255) / 256;    // 3125
    const int NB_G  = (NN * 4 + 255) / 256;    // 1563 (4 lanes per node)

    if (!s_side) {
        cudaStreamCreateWithFlags(&s_side, cudaStreamNonBlocking);
        cudaEventCreateWithFlags(&ev_fork, cudaEventDisableTiming);
        cudaEventCreateWithFlags(&ev_scan3, cudaEventDisableTiming);
        cudaEventCreateWithFlags(&ev_join, cudaEventDisableTiming);
    }

    // fork: side stream inherits capture dependency from the main stream
    cudaEventRecord(ev_fork, 0);
    cudaStreamWaitEvent(s_side, ev_fork, 0);

    // side chain: dense linear transform (independent of edge data)
    k_gemm1<<<dim3((NN + 511) / 512, KCH), 256, 0, s_side>>>(x, W1);

    // main chain: CSR build
    k_zero<<<NB_N, 256>>>();
    k_deg<<<NB_E4, 256>>>(dst);
    k_scan1<<<NSB, SCB>>>();
    k_scan3<<<NB_N, 256>>>();
    cudaEventRecord(ev_scan3, 0);
    k_fill<<<NB_E4, 256>>>(src, dst);

    // side: combine (needs gemm1 partials + dinv from scan3); overlaps fill
    cudaStreamWaitEvent(s_side, ev_scan3, 0);
    k_combine<<<NB_N, 256, 0, s_side>>>();
    cudaEventRecord(ev_join, s_side);

    // join: gathers need CSR (main) + feat (side)
    cudaStreamWaitEvent(0, ev_join, 0);

    k_gather<<<NB_G, 256>>>(b1, 0);   // layer 1 aggregate + relu + rescale
    k_gather<<<NB_G, 256>>>(b1, 1);   // layer 2 aggregate
    k_out<<<NB_N, 256>>>(W2, b2, out);
}